// round 9
// baseline (speedup 1.0000x reference)
#include <cuda_runtime.h>

#define B   8
#define C   1024
#define HW  4096
#define K   16

// Scratch (no allocations allowed) — fully rewritten every launch.
__device__ float g_num[B * K * C];      // masked class sums
__device__ float g_protoN[B * K * C];   // prototypes / (count * ||proto||)
__device__ int   g_counts[B * (K + 1)]; // per-class pixel counts (incl. class 0)

// ---------------------------------------------------------------------------
// K1: per-batch class histogram of the support mask
// ---------------------------------------------------------------------------
__global__ void __launch_bounds__(256) hist_kernel(const int* __restrict__ masks) {
    __shared__ int h[K + 1];
    const int b   = blockIdx.x;
    const int tid = threadIdx.x;
    if (tid <= K) h[tid] = 0;
    __syncthreads();
    for (int p = tid; p < HW; p += 256) {
        int v = masks[b * HW + p];
        if (v >= 0 && v <= K) atomicAdd(&h[v], 1);   // guarded: never traps
    }
    __syncthreads();
    if (tid <= K) g_counts[b * (K + 1) + tid] = h[tid];
}

// ---------------------------------------------------------------------------
// K2: masked per-class sums.  One warp = one channel; lane-private smem slots
// acc[class][tid] (bank = tid%32 -> conflict-free dynamic indexing).
// 2 float4 loads in flight per lane.  DRAM-bound (~128 MB).
// ---------------------------------------------------------------------------
__global__ void __launch_bounds__(256) proto_sum_kernel(
        const float* __restrict__ feat, const int* __restrict__ masks) {
    __shared__ unsigned char cls[HW];       // 4 KB
    __shared__ float acc[K][256];           // 16 KB

    const int b    = blockIdx.y;
    const int tid  = threadIdx.x;
    const int warp = tid >> 5;
    const int lane = tid & 31;
    const int c    = blockIdx.x * 8 + warp;

#pragma unroll
    for (int k = 0; k < K; k++) acc[k][tid] = 0.0f;
    for (int p = tid; p < HW; p += 256) {
        int v = masks[b * HW + p];
        cls[p] = (unsigned char)((v >= 1 && v <= K) ? v : 0);  // guarded
    }
    __syncthreads();

    const float4* f4 = (const float4*)(feat + ((size_t)b * C + c) * HW);
    const uchar4* c4 = (const uchar4*)cls;

    for (int i = lane; i < HW / 4; i += 64) {
        float4 v0 = f4[i];
        float4 v1 = f4[i + 32];
        uchar4 c0 = c4[i];
        uchar4 c1 = c4[i + 32];
        if (c0.x) acc[c0.x - 1][tid] += v0.x;
        if (c0.y) acc[c0.y - 1][tid] += v0.y;
        if (c0.z) acc[c0.z - 1][tid] += v0.z;
        if (c0.w) acc[c0.w - 1][tid] += v0.w;
        if (c1.x) acc[c1.x - 1][tid] += v1.x;
        if (c1.y) acc[c1.y - 1][tid] += v1.y;
        if (c1.z) acc[c1.z - 1][tid] += v1.z;
        if (c1.w) acc[c1.w - 1][tid] += v1.w;
    }

#pragma unroll
    for (int k = 0; k < K; k++) {
        float s = acc[k][tid];
#pragma unroll
        for (int off = 16; off; off >>= 1)
            s += __shfl_down_sync(0xffffffffu, s, off);
        if (lane == 0) g_num[((size_t)b * K + k) * C + c] = s;
    }
}

// ---------------------------------------------------------------------------
// K3: g_protoN = (num/count) / ||num/count||.
// argmax_k dot(protoN_k, q) == argmax_k cosine_sim.
// ---------------------------------------------------------------------------
__global__ void __launch_bounds__(256) finalize_kernel() {
    const int b = blockIdx.y, k = blockIdx.x, tid = threadIdx.x;
    const int cnt = g_counts[b * (K + 1) + k + 1];
    const float invCnt = cnt > 0 ? 1.0f / (float)cnt : 0.0f;
    const float* num = g_num    + ((size_t)(b * K + k)) * C;
    float*       out = g_protoN + ((size_t)(b * K + k)) * C;

    float pv[4];
    float ss = 0.0f;
#pragma unroll
    for (int j = 0; j < 4; j++) {
        pv[j] = num[tid + j * 256] * invCnt;
        ss += pv[j] * pv[j];
    }

    __shared__ float red[8];
    __shared__ float s_inv;
#pragma unroll
    for (int off = 16; off; off >>= 1)
        ss += __shfl_down_sync(0xffffffffu, ss, off);
    if ((tid & 31) == 0) red[tid >> 5] = ss;
    __syncthreads();
    if (tid == 0) {
        float s = 0.0f;
#pragma unroll
        for (int w = 0; w < 8; w++) s += red[w];
        s_inv = s > 0.0f ? 1.0f / sqrtf(s) : 0.0f;
    }
    __syncthreads();
    const float inv = s_inv;
#pragma unroll
    for (int j = 0; j < 4; j++) out[tid + j * 256] = pv[j] * inv;
}

// ---------------------------------------------------------------------------
// K4: double-buffered match.  Same slice geometry as R8 (512 thr = 8 slices
// x 64 px; slice = (k_half, channel_quarter); 8 protos x 256 ch per thread),
// but q loads are explicitly double-buffered: batch c+16's 16 LDGs issue
// BEFORE batch c's FFMA2 block, so DRAM latency is hidden by ILP.  No
// min-blocks cap -> ptxas gets ~90+ regs to hold both buffers in flight.
// Reduction order identical to R8 -> bit-identical results.
// ---------------------------------------------------------------------------
__device__ __forceinline__ void load_q16(const float* __restrict__ qb, int c,
                                         float* __restrict__ qv) {
#pragma unroll
    for (int j = 0; j < 16; j++)
        qv[j] = qb[(size_t)(c + j) * HW];
}

__device__ __forceinline__ void compute16(const float* __restrict__ spb,
                                          const float* __restrict__ qv,
                                          int c, unsigned long long* acc2) {
    unsigned long long qp[8];
#pragma unroll
    for (int j = 0; j < 8; j++)
        asm("mov.b64 %0, {%1, %2};" : "=l"(qp[j]) : "f"(qv[2*j]), "f"(qv[2*j+1]));
#pragma unroll
    for (int kk = 0; kk < 8; kk++) {
        const float* pb = spb + kk * C + c;
        const ulonglong2 p0 = *(const ulonglong2*)(pb + 0);   // LDS.128 bcast
        const ulonglong2 p1 = *(const ulonglong2*)(pb + 4);
        const ulonglong2 p2 = *(const ulonglong2*)(pb + 8);
        const ulonglong2 p3 = *(const ulonglong2*)(pb + 12);
        asm("fma.rn.f32x2 %0, %1, %2, %0;" : "+l"(acc2[kk]) : "l"(qp[0]), "l"(p0.x));
        asm("fma.rn.f32x2 %0, %1, %2, %0;" : "+l"(acc2[kk]) : "l"(qp[1]), "l"(p0.y));
        asm("fma.rn.f32x2 %0, %1, %2, %0;" : "+l"(acc2[kk]) : "l"(qp[2]), "l"(p1.x));
        asm("fma.rn.f32x2 %0, %1, %2, %0;" : "+l"(acc2[kk]) : "l"(qp[3]), "l"(p1.y));
        asm("fma.rn.f32x2 %0, %1, %2, %0;" : "+l"(acc2[kk]) : "l"(qp[4]), "l"(p2.x));
        asm("fma.rn.f32x2 %0, %1, %2, %0;" : "+l"(acc2[kk]) : "l"(qp[5]), "l"(p2.y));
        asm("fma.rn.f32x2 %0, %1, %2, %0;" : "+l"(acc2[kk]) : "l"(qp[6]), "l"(p3.x));
        asm("fma.rn.f32x2 %0, %1, %2, %0;" : "+l"(acc2[kk]) : "l"(qp[7]), "l"(p3.y));
    }
}

__global__ void __launch_bounds__(512) match_kernel(
        const float* __restrict__ q, float* __restrict__ out) {
    extern __shared__ __align__(16) char smem_raw[];
    float*              sp  = (float*)smem_raw;              // [K][C] = 64 KB
    unsigned long long* red = (unsigned long long*)smem_raw; // reuse: [64][16][4]

    const int b     = blockIdx.y;
    const int tid   = threadIdx.x;
    const int slice = tid >> 6;          // 0..7
    const int px    = tid & 63;          // 0..63
    const int kh    = slice & 1;         // k-half: protos [kh*8, kh*8+8)
    const int cq    = slice >> 1;        // channel quarter: [cq*256, cq*256+256)
    const int p     = blockIdx.x * 64 + px;

    // stage all 16x1024 normalized prototypes (L2-resident source, 512 KB)
    const float4* pr4 = (const float4*)(g_protoN + (size_t)b * K * C);
    for (int i = tid; i < K * C / 4; i += 512)
        ((float4*)sp)[i] = pr4[i];
    __syncthreads();

    const float* qb  = q + ((size_t)b * C + cq * 256) * HW + p;
    const float* spb = sp + (kh * 8) * C + cq * 256;

    unsigned long long acc2[8];
#pragma unroll
    for (int kk = 0; kk < 8; kk++) acc2[kk] = 0ull;

    float qA[16], qB[16];
    load_q16(qb, 0, qA);                          // prologue
#pragma unroll
    for (int c = 0; c < 256; c += 32) {
        load_q16(qb, c + 16, qB);                 // prefetch B while A computes
        compute16(spb, qA, c, acc2);
        if (c + 32 < 256) load_q16(qb, c + 32, qA);   // prefetch next A
        compute16(spb, qB, c + 16, acc2);
    }

    // protos dead -> packed partials red[px][k][quarter]
    __syncthreads();
    {
        unsigned long long* dst = red + ((size_t)px * K + kh * 8) * 4 + cq;
#pragma unroll
        for (int kk = 0; kk < 8; kk++) dst[kk * 4] = acc2[kk];
    }
    __syncthreads();

    // quarter reduction (q0+q1)+(q2+q3) packed, fold lo+hi last (== R8 order),
    // then first-max-wins argmax (jnp.argmax tie semantics)
    if (tid < 64) {
        const unsigned long long* r = red + (size_t)tid * K * 4;
        float best = -3.0e38f;
        int   bi   = 0;
#pragma unroll
        for (int k = 0; k < K; k++) {
            unsigned long long s01, s23, s;
            asm("add.rn.f32x2 %0, %1, %2;" : "=l"(s01) : "l"(r[k*4+0]), "l"(r[k*4+1]));
            asm("add.rn.f32x2 %0, %1, %2;" : "=l"(s23) : "l"(r[k*4+2]), "l"(r[k*4+3]));
            asm("add.rn.f32x2 %0, %1, %2;" : "=l"(s)   : "l"(s01),      "l"(s23));
            float lo, hi;
            asm("mov.b64 {%0, %1}, %2;" : "=f"(lo), "=f"(hi) : "l"(s));
            const float v = lo + hi;
            if (v > best) { best = v; bi = k; }
        }
        out[(size_t)b * HW + blockIdx.x * 64 + tid] = (float)bi;  // f32 output
    }
}

// ---------------------------------------------------------------------------
extern "C" void kernel_launch(void* const* d_in, const int* in_sizes, int n_in,
                              void* d_out, int out_size) {
    // masks is the unique B*HW = 32768-element input; its position fixes the
    // ordering of the two feature tensors.
    int mask_idx = 1;
    for (int i = 0; i < n_in; i++)
        if (in_sizes[i] == B * HW) { mask_idx = i; break; }

    const int*   masks = (const int*)d_in[mask_idx];
    const float* sfeat;
    const float* qfeat;
    if (mask_idx == 1)      { sfeat = (const float*)d_in[0]; qfeat = (const float*)d_in[2]; }
    else if (mask_idx == 2) { qfeat = (const float*)d_in[0]; sfeat = (const float*)d_in[1]; }
    else                    { qfeat = (const float*)d_in[1]; sfeat = (const float*)d_in[2]; }
    float* out = (float*)d_out;
    (void)out_size;

    hist_kernel<<<B, 256>>>(masks);
    proto_sum_kernel<<<dim3(C / 8, B), 256>>>(sfeat, masks);
    finalize_kernel<<<dim3(K, B), 256>>>();

    static int smem_set = 0;
    if (!smem_set) {
        cudaFuncSetAttribute(match_kernel,
                             cudaFuncAttributeMaxDynamicSharedMemorySize,
                             K * C * (int)sizeof(float));
        smem_set = 1;
    }
    match_kernel<<<dim3(HW / 64, B), 512, K * C * sizeof(float)>>>(qfeat, out);
}

// round 10
// speedup vs baseline: 1.4501x; 1.4501x over previous
#include <cuda_runtime.h>

#define B   8
#define C   1024
#define HW  4096
#define K   16

// Scratch (no allocations allowed) — fully rewritten every launch.
__device__ float g_num[B * K * C];      // masked class sums
__device__ float g_protoN[B * K * C];   // prototypes / (count * ||proto||)
__device__ int   g_counts[B * (K + 1)]; // per-class pixel counts (incl. class 0)

// ---------------------------------------------------------------------------
// K1: per-batch class histogram of the support mask
// ---------------------------------------------------------------------------
__global__ void __launch_bounds__(256) hist_kernel(const int* __restrict__ masks) {
    __shared__ int h[K + 1];
    const int b   = blockIdx.x;
    const int tid = threadIdx.x;
    if (tid <= K) h[tid] = 0;
    __syncthreads();
    for (int p = tid; p < HW; p += 256) {
        int v = masks[b * HW + p];
        if (v >= 0 && v <= K) atomicAdd(&h[v], 1);   // guarded: never traps
    }
    __syncthreads();
    if (tid <= K) g_counts[b * (K + 1) + tid] = h[tid];
}

// ---------------------------------------------------------------------------
// K2: masked per-class sums.  One warp = one channel; lane-private smem slots
// acc[class][tid] (bank = tid%32 -> conflict-free dynamic indexing).
// 4 float4 loads in flight per lane (2 KB/warp outstanding).
// ---------------------------------------------------------------------------
__global__ void __launch_bounds__(256) proto_sum_kernel(
        const float* __restrict__ feat, const int* __restrict__ masks) {
    __shared__ unsigned char cls[HW];       // 4 KB
    __shared__ float acc[K][256];           // 16 KB

    const int b    = blockIdx.y;
    const int tid  = threadIdx.x;
    const int warp = tid >> 5;
    const int lane = tid & 31;
    const int c    = blockIdx.x * 8 + warp;

#pragma unroll
    for (int k = 0; k < K; k++) acc[k][tid] = 0.0f;
    for (int p = tid; p < HW; p += 256) {
        int v = masks[b * HW + p];
        cls[p] = (unsigned char)((v >= 1 && v <= K) ? v : 0);  // guarded
    }
    __syncthreads();

    const float4* f4 = (const float4*)(feat + ((size_t)b * C + c) * HW);
    const uchar4* c4 = (const uchar4*)cls;

    for (int i = lane; i < HW / 4; i += 128) {
        float4 v0 = f4[i];
        float4 v1 = f4[i + 32];
        float4 v2 = f4[i + 64];
        float4 v3 = f4[i + 96];
        uchar4 m0 = c4[i];
        uchar4 m1 = c4[i + 32];
        uchar4 m2 = c4[i + 64];
        uchar4 m3 = c4[i + 96];
        if (m0.x) acc[m0.x - 1][tid] += v0.x;
        if (m0.y) acc[m0.y - 1][tid] += v0.y;
        if (m0.z) acc[m0.z - 1][tid] += v0.z;
        if (m0.w) acc[m0.w - 1][tid] += v0.w;
        if (m1.x) acc[m1.x - 1][tid] += v1.x;
        if (m1.y) acc[m1.y - 1][tid] += v1.y;
        if (m1.z) acc[m1.z - 1][tid] += v1.z;
        if (m1.w) acc[m1.w - 1][tid] += v1.w;
        if (m2.x) acc[m2.x - 1][tid] += v2.x;
        if (m2.y) acc[m2.y - 1][tid] += v2.y;
        if (m2.z) acc[m2.z - 1][tid] += v2.z;
        if (m2.w) acc[m2.w - 1][tid] += v2.w;
        if (m3.x) acc[m3.x - 1][tid] += v3.x;
        if (m3.y) acc[m3.y - 1][tid] += v3.y;
        if (m3.z) acc[m3.z - 1][tid] += v3.z;
        if (m3.w) acc[m3.w - 1][tid] += v3.w;
    }

#pragma unroll
    for (int k = 0; k < K; k++) {
        float s = acc[k][tid];
#pragma unroll
        for (int off = 16; off; off >>= 1)
            s += __shfl_down_sync(0xffffffffu, s, off);
        if (lane == 0) g_num[((size_t)b * K + k) * C + c] = s;
    }
}

// ---------------------------------------------------------------------------
// K3: g_protoN = (num/count) / ||num/count||.
// argmax_k dot(protoN_k, q) == argmax_k cosine_sim.
// ---------------------------------------------------------------------------
__global__ void __launch_bounds__(256) finalize_kernel() {
    const int b = blockIdx.y, k = blockIdx.x, tid = threadIdx.x;
    const int cnt = g_counts[b * (K + 1) + k + 1];
    const float invCnt = cnt > 0 ? 1.0f / (float)cnt : 0.0f;
    const float* num = g_num    + ((size_t)(b * K + k)) * C;
    float*       out = g_protoN + ((size_t)(b * K + k)) * C;

    float pv[4];
    float ss = 0.0f;
#pragma unroll
    for (int j = 0; j < 4; j++) {
        pv[j] = num[tid + j * 256] * invCnt;
        ss += pv[j] * pv[j];
    }

    __shared__ float red[8];
    __shared__ float s_inv;
#pragma unroll
    for (int off = 16; off; off >>= 1)
        ss += __shfl_down_sync(0xffffffffu, ss, off);
    if ((tid & 31) == 0) red[tid >> 5] = ss;
    __syncthreads();
    if (tid == 0) {
        float s = 0.0f;
#pragma unroll
        for (int w = 0; w < 8; w++) s += red[w];
        s_inv = s > 0.0f ? 1.0f / sqrtf(s) : 0.0f;
    }
    __syncthreads();
    const float inv = s_inv;
#pragma unroll
    for (int j = 0; j < 4; j++) out[tid + j * 256] = pv[j] * inv;
}

// ---------------------------------------------------------------------------
// K4: pixel-packed match.  Thread = (slice, t): slice = (k_half, ch_quarter),
// t covers 4 consecutive pixels.  q read as LDG.128 over pixels (512 B /warp
// /inst, fully coalesced) -> only 2-3 outstanding loads per warp saturate
// DRAM.  A float4 register quad is two f32x2 pixel-pairs for free; the proto
// scalar is duplicated with one mov.b64 per (k, channel).
// 256 thr/CTA, 256 CTAs, 64 KB smem -> 2 CTAs/SM.
// ---------------------------------------------------------------------------
__global__ void __launch_bounds__(256) match_kernel(
        const float* __restrict__ q, float* __restrict__ out) {
    extern __shared__ __align__(16) char smem_raw[];
    float*              sp  = (float*)smem_raw;              // [K][C] = 64 KB
    unsigned long long* red = (unsigned long long*)smem_raw; // reuse: 32 KB

    const int b     = blockIdx.y;
    const int tid   = threadIdx.x;
    const int slice = tid >> 5;          // 0..7
    const int t     = tid & 31;          // 0..31
    const int kh    = slice & 1;         // protos [kh*8, kh*8+8)
    const int cq    = slice >> 1;        // channels [cq*256, cq*256+256)
    const int p     = blockIdx.x * 128 + t * 4;   // 4 consecutive pixels

    // stage all 16x1024 normalized prototypes
    const float4* pr4 = (const float4*)(g_protoN + (size_t)b * K * C);
    for (int i = tid; i < K * C / 4; i += 256)
        ((float4*)sp)[i] = pr4[i];
    __syncthreads();

    const float* qb  = q + ((size_t)b * C + cq * 256) * HW + p;
    const float* spb = sp + (kh * 8) * C + cq * 256;

    unsigned long long acc2[8][2];   // [kk][pixel-pair]
#pragma unroll
    for (int kk = 0; kk < 8; kk++) { acc2[kk][0] = 0ull; acc2[kk][1] = 0ull; }

    for (int c = 0; c < 256; c += 4) {
        // 4 LDG.128 in flight: 2 KB/warp outstanding
        const float4 v0 = *(const float4*)&qb[(size_t)(c + 0) * HW];
        const float4 v1 = *(const float4*)&qb[(size_t)(c + 1) * HW];
        const float4 v2 = *(const float4*)&qb[(size_t)(c + 2) * HW];
        const float4 v3 = *(const float4*)&qb[(size_t)(c + 3) * HW];
        const ulonglong2 u0 = *(const ulonglong2*)&v0;   // (p0,p1),(p2,p3)
        const ulonglong2 u1 = *(const ulonglong2*)&v1;
        const ulonglong2 u2 = *(const ulonglong2*)&v2;
        const ulonglong2 u3 = *(const ulonglong2*)&v3;
#pragma unroll
        for (int kk = 0; kk < 8; kk++) {
            const float* pb = spb + kk * C + c;
            const float pk0 = pb[0], pk1 = pb[1], pk2 = pb[2], pk3 = pb[3];
            unsigned long long d0, d1, d2, d3;
            asm("mov.b64 %0, {%1, %1};" : "=l"(d0) : "f"(pk0));
            asm("mov.b64 %0, {%1, %1};" : "=l"(d1) : "f"(pk1));
            asm("mov.b64 %0, {%1, %1};" : "=l"(d2) : "f"(pk2));
            asm("mov.b64 %0, {%1, %1};" : "=l"(d3) : "f"(pk3));
            asm("fma.rn.f32x2 %0, %1, %2, %0;" : "+l"(acc2[kk][0]) : "l"(u0.x), "l"(d0));
            asm("fma.rn.f32x2 %0, %1, %2, %0;" : "+l"(acc2[kk][1]) : "l"(u0.y), "l"(d0));
            asm("fma.rn.f32x2 %0, %1, %2, %0;" : "+l"(acc2[kk][0]) : "l"(u1.x), "l"(d1));
            asm("fma.rn.f32x2 %0, %1, %2, %0;" : "+l"(acc2[kk][1]) : "l"(u1.y), "l"(d1));
            asm("fma.rn.f32x2 %0, %1, %2, %0;" : "+l"(acc2[kk][0]) : "l"(u2.x), "l"(d2));
            asm("fma.rn.f32x2 %0, %1, %2, %0;" : "+l"(acc2[kk][1]) : "l"(u2.y), "l"(d2));
            asm("fma.rn.f32x2 %0, %1, %2, %0;" : "+l"(acc2[kk][0]) : "l"(u3.x), "l"(d3));
            asm("fma.rn.f32x2 %0, %1, %2, %0;" : "+l"(acc2[kk][1]) : "l"(u3.y), "l"(d3));
        }
    }

    // protos dead -> partials in smem, lane-contiguous: red[k][pair][cs][t]
    __syncthreads();
#pragma unroll
    for (int kk = 0; kk < 8; kk++) {
        const int k = kh * 8 + kk;
        red[((k * 2 + 0) * 4 + cq) * 32 + t] = acc2[kk][0];
        red[((k * 2 + 1) * 4 + cq) * 32 + t] = acc2[kk][1];
    }
    __syncthreads();

    // one thread per pixel: sum 4 channel-quarters (packed), pick lane, argmax
    if (tid < 128) {
        const int tt   = tid >> 2;        // source thread
        const int pair = (tid >> 1) & 1;
        const int lohi = tid & 1;
        float best = -3.0e38f;
        int   bi   = 0;
#pragma unroll
        for (int k = 0; k < K; k++) {
            const unsigned long long* r = red + (k * 2 + pair) * 4 * 32 + tt;
            unsigned long long s01, s23, s;
            asm("add.rn.f32x2 %0, %1, %2;" : "=l"(s01) : "l"(r[0]),   "l"(r[32]));
            asm("add.rn.f32x2 %0, %1, %2;" : "=l"(s23) : "l"(r[64]),  "l"(r[96]));
            asm("add.rn.f32x2 %0, %1, %2;" : "=l"(s)   : "l"(s01),    "l"(s23));
            float lo, hi;
            asm("mov.b64 {%0, %1}, %2;" : "=f"(lo), "=f"(hi) : "l"(s));
            const float v = lohi ? hi : lo;
            if (v > best) { best = v; bi = k; }
        }
        out[(size_t)b * HW + blockIdx.x * 128 + tid] = (float)bi;  // f32 output
    }
}

// ---------------------------------------------------------------------------
extern "C" void kernel_launch(void* const* d_in, const int* in_sizes, int n_in,
                              void* d_out, int out_size) {
    // masks is the unique B*HW = 32768-element input; its position fixes the
    // ordering of the two feature tensors.
    int mask_idx = 1;
    for (int i = 0; i < n_in; i++)
        if (in_sizes[i] == B * HW) { mask_idx = i; break; }

    const int*   masks = (const int*)d_in[mask_idx];
    const float* sfeat;
    const float* qfeat;
    if (mask_idx == 1)      { sfeat = (const float*)d_in[0]; qfeat = (const float*)d_in[2]; }
    else if (mask_idx == 2) { qfeat = (const float*)d_in[0]; sfeat = (const float*)d_in[1]; }
    else                    { qfeat = (const float*)d_in[1]; sfeat = (const float*)d_in[2]; }
    float* out = (float*)d_out;
    (void)out_size;

    hist_kernel<<<B, 256>>>(masks);
    proto_sum_kernel<<<dim3(C / 8, B), 256>>>(sfeat, masks);
    finalize_kernel<<<dim3(K, B), 256>>>();

    static int smem_set = 0;
    if (!smem_set) {
        cudaFuncSetAttribute(match_kernel,
                             cudaFuncAttributeMaxDynamicSharedMemorySize,
                             K * C * (int)sizeof(float));
        smem_set = 1;
    }
    match_kernel<<<dim3(HW / 128, B), 256, K * C * sizeof(float)>>>(qfeat, out);
}

// round 11
// speedup vs baseline: 1.7683x; 1.2194x over previous
#include <cuda_runtime.h>

#define B   8
#define C   1024
#define HW  4096
#define K   16

// Scratch (no allocations allowed) — fully rewritten every launch.
__device__ float g_num[B * K * C];      // masked class sums
__device__ float g_protoN[B * K * C];   // prototypes / (count * ||proto||)
__device__ int   g_counts[B * (K + 1)]; // per-class pixel counts (incl. class 0)

// ---------------------------------------------------------------------------
// K1: per-batch class histogram of the support mask
// ---------------------------------------------------------------------------
__global__ void __launch_bounds__(256) hist_kernel(const int* __restrict__ masks) {
    __shared__ int h[K + 1];
    const int b   = blockIdx.x;
    const int tid = threadIdx.x;
    if (tid <= K) h[tid] = 0;
    __syncthreads();
    for (int p = tid; p < HW; p += 256) {
        int v = masks[b * HW + p];
        if (v >= 0 && v <= K) atomicAdd(&h[v], 1);   // guarded: never traps
    }
    __syncthreads();
    if (tid <= K) g_counts[b * (K + 1) + tid] = h[tid];
}

// ---------------------------------------------------------------------------
// K2: masked per-class sums.  One warp = one channel; lane-private smem slots
// acc[class][tid] (bank = tid%32 -> conflict-free dynamic indexing).
// 4 float4 loads in flight per lane (2 KB/warp outstanding).
// ---------------------------------------------------------------------------
__global__ void __launch_bounds__(256) proto_sum_kernel(
        const float* __restrict__ feat, const int* __restrict__ masks) {
    __shared__ unsigned char cls[HW];       // 4 KB
    __shared__ float acc[K][256];           // 16 KB

    const int b    = blockIdx.y;
    const int tid  = threadIdx.x;
    const int warp = tid >> 5;
    const int lane = tid & 31;
    const int c    = blockIdx.x * 8 + warp;

#pragma unroll
    for (int k = 0; k < K; k++) acc[k][tid] = 0.0f;
    for (int p = tid; p < HW; p += 256) {
        int v = masks[b * HW + p];
        cls[p] = (unsigned char)((v >= 1 && v <= K) ? v : 0);  // guarded
    }
    __syncthreads();

    const float4* f4 = (const float4*)(feat + ((size_t)b * C + c) * HW);
    const uchar4* c4 = (const uchar4*)cls;

    for (int i = lane; i < HW / 4; i += 128) {
        float4 v0 = f4[i];
        float4 v1 = f4[i + 32];
        float4 v2 = f4[i + 64];
        float4 v3 = f4[i + 96];
        uchar4 m0 = c4[i];
        uchar4 m1 = c4[i + 32];
        uchar4 m2 = c4[i + 64];
        uchar4 m3 = c4[i + 96];
        if (m0.x) acc[m0.x - 1][tid] += v0.x;
        if (m0.y) acc[m0.y - 1][tid] += v0.y;
        if (m0.z) acc[m0.z - 1][tid] += v0.z;
        if (m0.w) acc[m0.w - 1][tid] += v0.w;
        if (m1.x) acc[m1.x - 1][tid] += v1.x;
        if (m1.y) acc[m1.y - 1][tid] += v1.y;
        if (m1.z) acc[m1.z - 1][tid] += v1.z;
        if (m1.w) acc[m1.w - 1][tid] += v1.w;
        if (m2.x) acc[m2.x - 1][tid] += v2.x;
        if (m2.y) acc[m2.y - 1][tid] += v2.y;
        if (m2.z) acc[m2.z - 1][tid] += v2.z;
        if (m2.w) acc[m2.w - 1][tid] += v2.w;
        if (m3.x) acc[m3.x - 1][tid] += v3.x;
        if (m3.y) acc[m3.y - 1][tid] += v3.y;
        if (m3.z) acc[m3.z - 1][tid] += v3.z;
        if (m3.w) acc[m3.w - 1][tid] += v3.w;
    }

#pragma unroll
    for (int k = 0; k < K; k++) {
        float s = acc[k][tid];
#pragma unroll
        for (int off = 16; off; off >>= 1)
            s += __shfl_down_sync(0xffffffffu, s, off);
        if (lane == 0) g_num[((size_t)b * K + k) * C + c] = s;
    }
}

// ---------------------------------------------------------------------------
// K3: g_protoN = (num/count) / ||num/count||.
// argmax_k dot(protoN_k, q) == argmax_k cosine_sim.
// ---------------------------------------------------------------------------
__global__ void __launch_bounds__(256) finalize_kernel() {
    const int b = blockIdx.y, k = blockIdx.x, tid = threadIdx.x;
    const int cnt = g_counts[b * (K + 1) + k + 1];
    const float invCnt = cnt > 0 ? 1.0f / (float)cnt : 0.0f;
    const float* num = g_num    + ((size_t)(b * K + k)) * C;
    float*       out = g_protoN + ((size_t)(b * K + k)) * C;

    float pv[4];
    float ss = 0.0f;
#pragma unroll
    for (int j = 0; j < 4; j++) {
        pv[j] = num[tid + j * 256] * invCnt;
        ss += pv[j] * pv[j];
    }

    __shared__ float red[8];
    __shared__ float s_inv;
#pragma unroll
    for (int off = 16; off; off >>= 1)
        ss += __shfl_down_sync(0xffffffffu, ss, off);
    if ((tid & 31) == 0) red[tid >> 5] = ss;
    __syncthreads();
    if (tid == 0) {
        float s = 0.0f;
#pragma unroll
        for (int w = 0; w < 8; w++) s += red[w];
        s_inv = s > 0.0f ? 1.0f / sqrtf(s) : 0.0f;
    }
    __syncthreads();
    const float inv = s_inv;
#pragma unroll
    for (int j = 0; j < 4; j++) out[tid + j * 256] = pv[j] * inv;
}

// ---------------------------------------------------------------------------
// K4: pixel-packed match with software-pipelined q loads.
// Thread = (slice, t): slice = (k_half, ch_quarter), t covers 4 consecutive
// pixels; q read via LDG.128 over pixels.  A/B double buffer: batch c+4's
// 4 LDG.128 are issued before batch c's FFMA2 block, so DRAM latency hides
// under ~220+ cycles of compute issue.  __launch_bounds__(256, 2) keeps the
// guaranteed 2 CTAs/SM while giving ptxas a 128-reg budget for the buffers.
// Proto reads are LDS.128.  Reduction order identical to R10.
// ---------------------------------------------------------------------------
__device__ __forceinline__ void fma_batch(
        const float* __restrict__ spb, int c,
        const float4& v0, const float4& v1, const float4& v2, const float4& v3,
        unsigned long long (&acc2)[8][2]) {
    const ulonglong2 u0 = *(const ulonglong2*)&v0;   // (p0,p1),(p2,p3)
    const ulonglong2 u1 = *(const ulonglong2*)&v1;
    const ulonglong2 u2 = *(const ulonglong2*)&v2;
    const ulonglong2 u3 = *(const ulonglong2*)&v3;
#pragma unroll
    for (int kk = 0; kk < 8; kk++) {
        const float4 pk = *(const float4*)(spb + kk * C + c);  // LDS.128 bcast
        unsigned long long d0, d1, d2, d3;
        asm("mov.b64 %0, {%1, %1};" : "=l"(d0) : "f"(pk.x));
        asm("mov.b64 %0, {%1, %1};" : "=l"(d1) : "f"(pk.y));
        asm("mov.b64 %0, {%1, %1};" : "=l"(d2) : "f"(pk.z));
        asm("mov.b64 %0, {%1, %1};" : "=l"(d3) : "f"(pk.w));
        asm("fma.rn.f32x2 %0, %1, %2, %0;" : "+l"(acc2[kk][0]) : "l"(u0.x), "l"(d0));
        asm("fma.rn.f32x2 %0, %1, %2, %0;" : "+l"(acc2[kk][1]) : "l"(u0.y), "l"(d0));
        asm("fma.rn.f32x2 %0, %1, %2, %0;" : "+l"(acc2[kk][0]) : "l"(u1.x), "l"(d1));
        asm("fma.rn.f32x2 %0, %1, %2, %0;" : "+l"(acc2[kk][1]) : "l"(u1.y), "l"(d1));
        asm("fma.rn.f32x2 %0, %1, %2, %0;" : "+l"(acc2[kk][0]) : "l"(u2.x), "l"(d2));
        asm("fma.rn.f32x2 %0, %1, %2, %0;" : "+l"(acc2[kk][1]) : "l"(u2.y), "l"(d2));
        asm("fma.rn.f32x2 %0, %1, %2, %0;" : "+l"(acc2[kk][0]) : "l"(u3.x), "l"(d3));
        asm("fma.rn.f32x2 %0, %1, %2, %0;" : "+l"(acc2[kk][1]) : "l"(u3.y), "l"(d3));
    }
}

__global__ void __launch_bounds__(256, 2) match_kernel(
        const float* __restrict__ q, float* __restrict__ out) {
    extern __shared__ __align__(16) char smem_raw[];
    float*              sp  = (float*)smem_raw;              // [K][C] = 64 KB
    unsigned long long* red = (unsigned long long*)smem_raw; // reuse: 32 KB

    const int b     = blockIdx.y;
    const int tid   = threadIdx.x;
    const int slice = tid >> 5;          // 0..7
    const int t     = tid & 31;          // 0..31
    const int kh    = slice & 1;         // protos [kh*8, kh*8+8)
    const int cq    = slice >> 1;        // channels [cq*256, cq*256+256)
    const int p     = blockIdx.x * 128 + t * 4;   // 4 consecutive pixels

    // stage all 16x1024 normalized prototypes
    const float4* pr4 = (const float4*)(g_protoN + (size_t)b * K * C);
    for (int i = tid; i < K * C / 4; i += 256)
        ((float4*)sp)[i] = pr4[i];
    __syncthreads();

    const float* qb  = q + ((size_t)b * C + cq * 256) * HW + p;
    const float* spb = sp + (kh * 8) * C + cq * 256;

    unsigned long long acc2[8][2];   // [kk][pixel-pair]
#pragma unroll
    for (int kk = 0; kk < 8; kk++) { acc2[kk][0] = 0ull; acc2[kk][1] = 0ull; }

    // prologue: batch A = channels 0..3
    float4 a0 = *(const float4*)&qb[(size_t)0 * HW];
    float4 a1 = *(const float4*)&qb[(size_t)1 * HW];
    float4 a2 = *(const float4*)&qb[(size_t)2 * HW];
    float4 a3 = *(const float4*)&qb[(size_t)3 * HW];

#pragma unroll 4
    for (int c = 0; c < 256; c += 8) {
        // prefetch batch B (c+4) before computing A
        float4 b0 = *(const float4*)&qb[(size_t)(c + 4) * HW];
        float4 b1 = *(const float4*)&qb[(size_t)(c + 5) * HW];
        float4 b2 = *(const float4*)&qb[(size_t)(c + 6) * HW];
        float4 b3 = *(const float4*)&qb[(size_t)(c + 7) * HW];
        fma_batch(spb, c, a0, a1, a2, a3, acc2);

        // prefetch next A (c+8) before computing B; guard the tail
        if (c + 8 < 256) {
            a0 = *(const float4*)&qb[(size_t)(c +  8) * HW];
            a1 = *(const float4*)&qb[(size_t)(c +  9) * HW];
            a2 = *(const float4*)&qb[(size_t)(c + 10) * HW];
            a3 = *(const float4*)&qb[(size_t)(c + 11) * HW];
        }
        fma_batch(spb, c + 4, b0, b1, b2, b3, acc2);
    }

    // protos dead -> partials in smem, lane-contiguous: red[k][pair][cs][t]
    __syncthreads();
#pragma unroll
    for (int kk = 0; kk < 8; kk++) {
        const int k = kh * 8 + kk;
        red[((k * 2 + 0) * 4 + cq) * 32 + t] = acc2[kk][0];
        red[((k * 2 + 1) * 4 + cq) * 32 + t] = acc2[kk][1];
    }
    __syncthreads();

    // one thread per pixel: sum 4 channel-quarters (packed), pick lane, argmax
    if (tid < 128) {
        const int tt   = tid >> 2;        // source thread
        const int pair = (tid >> 1) & 1;
        const int lohi = tid & 1;
        float best = -3.0e38f;
        int   bi   = 0;
#pragma unroll
        for (int k = 0; k < K; k++) {
            const unsigned long long* r = red + (k * 2 + pair) * 4 * 32 + tt;
            unsigned long long s01, s23, s;
            asm("add.rn.f32x2 %0, %1, %2;" : "=l"(s01) : "l"(r[0]),   "l"(r[32]));
            asm("add.rn.f32x2 %0, %1, %2;" : "=l"(s23) : "l"(r[64]),  "l"(r[96]));
            asm("add.rn.f32x2 %0, %1, %2;" : "=l"(s)   : "l"(s01),    "l"(s23));
            float lo, hi;
            asm("mov.b64 {%0, %1}, %2;" : "=f"(lo), "=f"(hi) : "l"(s));
            const float v = lohi ? hi : lo;
            if (v > best) { best = v; bi = k; }
        }
        out[(size_t)b * HW + blockIdx.x * 128 + tid] = (float)bi;  // f32 output
    }
}

// ---------------------------------------------------------------------------
extern "C" void kernel_launch(void* const* d_in, const int* in_sizes, int n_in,
                              void* d_out, int out_size) {
    // masks is the unique B*HW = 32768-element input; its position fixes the
    // ordering of the two feature tensors.
    int mask_idx = 1;
    for (int i = 0; i < n_in; i++)
        if (in_sizes[i] == B * HW) { mask_idx = i; break; }

    const int*   masks = (const int*)d_in[mask_idx];
    const float* sfeat;
    const float* qfeat;
    if (mask_idx == 1)      { sfeat = (const float*)d_in[0]; qfeat = (const float*)d_in[2]; }
    else if (mask_idx == 2) { qfeat = (const float*)d_in[0]; sfeat = (const float*)d_in[1]; }
    else                    { qfeat = (const float*)d_in[1]; sfeat = (const float*)d_in[2]; }
    float* out = (float*)d_out;
    (void)out_size;

    hist_kernel<<<B, 256>>>(masks);
    proto_sum_kernel<<<dim3(C / 8, B), 256>>>(sfeat, masks);
    finalize_kernel<<<dim3(K, B), 256>>>();

    static int smem_set = 0;
    if (!smem_set) {
        cudaFuncSetAttribute(match_kernel,
                             cudaFuncAttributeMaxDynamicSharedMemorySize,
                             K * C * (int)sizeof(float));
        smem_set = 1;
    }
    match_kernel<<<dim3(HW / 128, B), 256, K * C * sizeof(float)>>>(qfeat, out);
}